// round 17
// baseline (speedup 1.0000x reference)
#include <cuda_runtime.h>
#include <cstdint>

#define CIN   80
#define COUT  32
#define BATCH 8
#define HH    160
#define WW    320
#define DD    48
#define HW    (HH*WW)      // 51200
#define NROWS 2560         // (b,h,img) rows
#define K1_RPB 6           // rows per K1 block
#define K1_GRID 427        // 427*6 = 2562 >= 2560

typedef unsigned long long ull;

// feature scratch: [img][b][o][h][w]; L features pre-scaled by 1/32
__device__ float g_feat[2u * BATCH * COUT * HW];
// folded weights (splatted f32x2) + bias
__device__ ull g_sW[CIN * COUT];
__device__ ull g_sB[COUT];

__device__ __forceinline__ ull fma2(ull a, ull b, ull c) {
    ull d;
    asm("fma.rn.f32x2 %0, %1, %2, %3;" : "=l"(d) : "l"(a), "l"(b), "l"(c));
    return d;
}
__device__ __forceinline__ ull mul2(ull a, ull b) {
    ull d;
    asm("mul.rn.f32x2 %0, %1, %2;" : "=l"(d) : "l"(a), "l"(b));
    return d;
}
__device__ __forceinline__ ull pack2(float lo, float hi) {
    ull d;
    asm("mov.b64 %0, {%1, %2};" : "=l"(d) : "f"(lo), "f"(hi));
    return d;
}
__device__ __forceinline__ uint32_t s2u(const void* p) {
    uint32_t a;
    asm("{ .reg .u64 t; cvta.to.shared.u64 t, %1; cvt.u32.u64 %0, t; }" : "=r"(a) : "l"(p));
    return a;
}
__device__ __forceinline__ void bulk1d(uint32_t dst, const void* src, uint32_t bytes, uint32_t mbar) {
    asm volatile("cp.async.bulk.shared::cluster.global.mbarrier::complete_tx::bytes [%0], [%1], %2, [%3];"
                 :: "r"(dst), "l"(src), "r"(bytes), "r"(mbar) : "memory");
}
__device__ __forceinline__ void mbar_init(uint32_t mbar, uint32_t cnt) {
    asm volatile("mbarrier.init.shared.b64 [%0], %1;" :: "r"(mbar), "r"(cnt) : "memory");
}
__device__ __forceinline__ void mbar_expect(uint32_t mbar, uint32_t tx) {
    asm volatile("mbarrier.arrive.expect_tx.shared.b64 _, [%0], %1;" :: "r"(mbar), "r"(tx) : "memory");
}
__device__ __forceinline__ void mbar_wait(uint32_t mbar, uint32_t parity) {
    uint32_t done;
    asm volatile("{\n\t.reg .pred p;\n\t"
                 "mbarrier.try_wait.parity.acquire.cta.shared::cta.b64 p, [%1], %2;\n\t"
                 "selp.b32 %0, 1, 0, p;\n\t}" : "=r"(done) : "r"(mbar), "r"(parity) : "memory");
    while (!done) {
        asm volatile("{\n\t.reg .pred p;\n\t"
                     "mbarrier.try_wait.parity.acquire.cta.shared::cta.b64 p, [%1], %2, 0x989680;\n\t"
                     "selp.b32 %0, 1, 0, p;\n\t}" : "=r"(done) : "r"(mbar), "r"(parity) : "memory");
    }
}

// ===========================================================================
// K0: fold BN into conv weights, once.
// ===========================================================================
__global__ void fold_kernel(
    const float* __restrict__ bg, const float* __restrict__ bb,
    const float* __restrict__ bm, const float* __restrict__ bv,
    const float* __restrict__ cw, const float* __restrict__ cb)
{
    const int tid = threadIdx.x;
    for (int idx = tid; idx < CIN * COUT; idx += 256) {
        int c = idx >> 5, o = idx & 31;
        float sc = bg[c] * rsqrtf(bv[c] + 1e-5f);
        float wv = cw[o * CIN + c] * sc;
        g_sW[idx] = pack2(wv, wv);
    }
    if (tid < COUT) {
        float s = cb[tid];
        for (int c = 0; c < CIN; c++) {
            float sc = bg[c] * rsqrtf(bv[c] + 1e-5f);
            s += cw[tid * CIN + c] * (bb[c] - bm[c] * sc);
        }
        g_sB[tid] = pack2(s, s);
    }
}

// ===========================================================================
// K1: preconv, persistent-ish. 427 blocks x 6 rows; continuous TMA chunk
// stream across rows (30 chunks, 2 buffers). Thread = (u, og): float4 at
// col 4u, outputs og*8..og*8+7; 16 ull accs. 3 CTAs/SM.
// ===========================================================================
#define K1_CHUNK  16
#define K1_BUF    (K1_CHUNK * WW * 4)      // 20480 B
#define K1_OFF_SB   20480
#define K1_OFF_MBAR 20736
#define K1_OFF_STG  20752
#define K1_SMEM   (K1_OFF_STG + 2 * K1_BUF)   // 61712

__global__ __launch_bounds__(320, 3) void preconv_kernel(
    const float* __restrict__ inL, const float* __restrict__ inR)
{
    extern __shared__ char smraw[];
    ull*   sW    = (ull*)smraw;                     // [80][32] splatted
    ull*   sB    = (ull*)(smraw + K1_OFF_SB);       // [32]
    float* stage = (float*)(smraw + K1_OFF_STG);
    const uint32_t smbase = s2u(smraw);
    const uint32_t mb0 = smbase + K1_OFF_MBAR;

    const int tid = threadIdx.x;
    const int r0  = blockIdx.x * K1_RPB;
    const int nrows = (NROWS - r0 < K1_RPB) ? (NROWS - r0) : K1_RPB;
    const int Q = nrows * 5;                  // total chunks this block

    if (tid == 0) { mbar_init(mb0, 1); mbar_init(mb0 + 8, 1); }
    // weights once per block
    {
        const ulonglong2* src = (const ulonglong2*)g_sW;
        ulonglong2* dst = (ulonglong2*)sW;
        for (int i = tid; i < CIN * COUT / 2; i += 320) dst[i] = src[i];
        if (tid < COUT) sB[tid] = g_sB[tid];
    }
    __syncthreads();

    // chunk q -> row r0 + q/5, channel-block (q%5)*16
    auto rowptr = [&](int q) -> const float* {
        int r   = r0 + q / 5;
        int img = r & 1;
        int bh  = r >> 1;
        int h = bh % HH, b = bh / HH;
        const float* in = img ? inR : inL;
        return in + (long)b * CIN * HW + (long)h * WW + (long)((q % 5) * K1_CHUNK) * HW;
    };

    if (tid == 0) {
        #pragma unroll
        for (int q = 0; q < 2; q++) {
            uint32_t mbar = mb0 + (q & 1) * 8;
            mbar_expect(mbar, (uint32_t)K1_BUF);
            uint32_t dst = smbase + K1_OFF_STG + (q & 1) * K1_BUF;
            const float* src = rowptr(q);
            for (int cc = 0; cc < K1_CHUNK; cc++)
                bulk1d(dst + cc * 1280, src + (long)cc * HW, 1280, mbar);
        }
    }

    const int u  = tid % 80;
    const int og = tid / 80;              // 0..3
    const ull inv2 = pack2(0.03125f, 0.03125f);

    for (int rr = 0; rr < nrows; rr++) {
        ull a0[8], a1[8];
        #pragma unroll
        for (int oo = 0; oo < 8; oo++) { a0[oo] = sB[og * 8 + oo]; a1[oo] = a0[oo]; }

        for (int k = 0; k < 5; k++) {
            const int q = rr * 5 + k;
            const int s = q & 1;
            mbar_wait(mb0 + s * 8, (q >> 1) & 1);
            const float* bufD = stage + s * (K1_BUF / 4) + 4 * u;

            #pragma unroll 4
            for (int cc = 0; cc < K1_CHUNK; cc++) {
                float4 xv = *(const float4*)(bufD + cc * WW);           // LDS.128
                ull x01 = pack2(fmaxf(xv.x, 0.f), fmaxf(xv.y, 0.f));
                ull x23 = pack2(fmaxf(xv.z, 0.f), fmaxf(xv.w, 0.f));
                const ulonglong2* wr = (const ulonglong2*)&sW[(k * K1_CHUNK + cc) * 32 + og * 8];
                #pragma unroll
                for (int j = 0; j < 4; j++) {
                    ulonglong2 W2 = wr[j];        // broadcast LDS.128
                    a0[2*j]   = fma2(x01, W2.x, a0[2*j]);
                    a1[2*j]   = fma2(x23, W2.x, a1[2*j]);
                    a0[2*j+1] = fma2(x01, W2.y, a0[2*j+1]);
                    a1[2*j+1] = fma2(x23, W2.y, a1[2*j+1]);
                }
            }
            __syncthreads();   // buffer s fully consumed by all warps
            if (tid == 0 && q + 2 < Q) {
                uint32_t mbar = mb0 + s * 8;
                mbar_expect(mbar, (uint32_t)K1_BUF);
                uint32_t dst = smbase + K1_OFF_STG + s * K1_BUF;
                const float* src = rowptr(q + 2);
                for (int cc = 0; cc < K1_CHUNK; cc++)
                    bulk1d(dst + cc * 1280, src + (long)cc * HW, 1280, mbar);
            }
        }

        // store this row's features
        const int r   = r0 + rr;
        const int img = r & 1;
        const int bh  = r >> 1;
        const int h = bh % HH, b = bh / HH;
        if (img == 0) {   // L carries the 1/32 mean factor
            #pragma unroll
            for (int oo = 0; oo < 8; oo++) { a0[oo] = mul2(a0[oo], inv2); a1[oo] = mul2(a1[oo], inv2); }
        }
        float* outp = g_feat + (long)img * (BATCH * COUT * HW)
                    + (long)b * COUT * HW + (long)h * WW + 4 * u;
        #pragma unroll
        for (int oo = 0; oo < 8; oo++) {
            ulonglong2 v; v.x = a0[oo]; v.y = a1[oo];
            *(ulonglong2*)(outp + (long)(og * 8 + oo) * HW) = v;   // STG.128
        }
    }
}

// ===========================================================================
// K2: correlation, half-row. One block per (b,h,half); 3 CTAs/SM, 30 warps.
// smem: mbar(16) + Ls[32][160] + RA[32][208] = 47120 B.
// Thread = (wq, ig): 4 w x 6 disparities (R11-verified template).
// ===========================================================================
#define WH   160
#define RW   208
#define K2_SMEM (16 + (32*WH + 32*RW) * 4)   // 47120

template <int BASE>
__device__ __forceinline__ void corr_accum(const ull* __restrict__ V, ull LpX, ull LpY,
                                           ull* __restrict__ aP, ull* __restrict__ aQ)
{
    #pragma unroll
    for (int dd = 0; dd < 6; dd++) {
        ull v0, v1;
        if ((dd & 1) == 0) {
            v0 = V[(BASE - dd) / 2];
            v1 = V[(BASE + 2 - dd) / 2];
        } else {
            const float2* a  = (const float2*)&V[(BASE - 1 - dd) / 2];
            const float2* bq = (const float2*)&V[(BASE + 1 - dd) / 2];
            const float2* cq = (const float2*)&V[(BASE + 3 - dd) / 2];
            v0 = pack2(a->y, bq->x);
            v1 = pack2(bq->y, cq->x);
        }
        aP[dd] = fma2(LpX, v0, aP[dd]);
        aQ[dd] = fma2(LpY, v1, aQ[dd]);
    }
}

__global__ __launch_bounds__(320, 3) void corr_kernel(float* __restrict__ out)
{
    extern __shared__ char smraw[];
    float* Ls = (float*)(smraw + 16);     // [32][160] (already scaled by 1/32)
    float* RA = Ls + 32 * WH;             // [32][208]; RA[o][j] = R[half*160-48+j]
    const uint32_t mbar = s2u(smraw);

    const int tid  = threadIdx.x;
    const int bid  = blockIdx.x;
    const int half = bid & 1;
    const int bh   = bid >> 1;
    const int h    = bh % HH, b = bh / HH;
    const float* fL = g_feat + (long)b * COUT * HW + (long)h * WW + half * WH;
    const float* fR = g_feat + (long)(BATCH * COUT) * HW
                    + (long)b * COUT * HW + (long)h * WW + (half ? WH - 48 : 0);

    if (tid == 0) {
        mbar_init(mbar, 1);
        asm volatile("fence.proxy.async.shared::cta;" ::: "memory");
        const uint32_t rbytes = half ? 832u : 640u;   // 208 or 160 floats of R
        mbar_expect(mbar, 32 * (640 + rbytes));
        uint32_t lsb = s2u(Ls), rab = s2u(RA);
        for (int o = 0; o < 32; o++) {
            bulk1d(lsb + o * (WH * 4), fL + (long)o * HW, 640, mbar);
            bulk1d(rab + o * (RW * 4) + (half ? 0 : 192), fR + (long)o * HW, rbytes, mbar);
        }
    }
    // half==0: zero R halo cols [0,48) while TMA is in flight
    if (half == 0) {
        for (int idx = tid; idx < 32 * 48; idx += 320) {
            int o = idx / 48, j = idx % 48;
            RA[o * RW + j] = 0.f;
        }
    }
    __syncthreads();
    mbar_wait(mbar, 0);

    const int wq = tid % 40, ig = tid / 40;   // ig 0..7
    const int W0 = 4 * wq;
    const int i0 = 6 * ig;
    const int rb = W0 + ((43 - i0) & ~3);     // 16B-aligned V window base

    ull aP[6], aQ[6];
    #pragma unroll
    for (int d = 0; d < 6; d++) { aP[d] = 0ULL; aQ[d] = 0ULL; }

    #pragma unroll 4
    for (int c = 0; c < 32; c++) {
        ulonglong2 Lp = *(const ulonglong2*)&Ls[c * WH + W0];
        const float* rr = &RA[c * RW + rb];
        ull V[6];
        #pragma unroll
        for (int m = 0; m < 3; m++) {
            ulonglong2 t2 = *(const ulonglong2*)&rr[4 * m];   // LDS.128
            V[2*m] = t2.x; V[2*m+1] = t2.y;
        }
        if (ig & 1) corr_accum<6>(V, Lp.x, Lp.y, aP, aQ);
        else        corr_accum<8>(V, Lp.x, Lp.y, aP, aQ);
    }

    float* outp = out + ((long)(b * DD + i0) * HH + h) * WW + half * WH + W0;
    #pragma unroll
    for (int dd = 0; dd < 6; dd++) {
        float2 p = *(float2*)&aP[dd];
        float2 q = *(float2*)&aQ[dd];
        float4 v; v.x = p.x; v.y = p.y; v.z = q.x; v.w = q.y;
        *(float4*)&outp[(long)dd * HW] = v;     // STG.128
    }
}

// ---------------------------------------------------------------------------
extern "C" void kernel_launch(void* const* d_in, const int* in_sizes, int n_in,
                              void* d_out, int out_size)
{
    const float* fL = (const float*)d_in[0];
    const float* fR = (const float*)d_in[1];
    const float* bg = (const float*)d_in[2];
    const float* bb = (const float*)d_in[3];
    const float* bm = (const float*)d_in[4];
    const float* bv = (const float*)d_in[5];
    const float* cw = (const float*)d_in[6];
    const float* cb = (const float*)d_in[7];
    float* out = (float*)d_out;

    cudaFuncSetAttribute(preconv_kernel, cudaFuncAttributeMaxDynamicSharedMemorySize, K1_SMEM);
    cudaFuncSetAttribute(corr_kernel,    cudaFuncAttributeMaxDynamicSharedMemorySize, K2_SMEM);
    fold_kernel<<<1, 256>>>(bg, bb, bm, bv, cw, cb);
    preconv_kernel<<<K1_GRID, 320, K1_SMEM>>>(fL, fR);
    corr_kernel<<<2 * BATCH * HH, 320, K2_SMEM>>>(out);
}